// round 7
// baseline (speedup 1.0000x reference)
#include <cuda_runtime.h>

// cos(pi*t/16) constants
#define CC1 0.98078528040323044913f
#define CC2 0.92387953251128675613f
#define CC3 0.83146961230254523708f
#define CC4 0.70710678118654752440f
#define CC5 0.55557023301960222474f
#define CC6 0.38268343236508977173f
#define CC7 0.19509032201612826785f

typedef unsigned long long u64;

__device__ __forceinline__ u64 pack2(float lo, float hi) {
    u64 r; asm("mov.b64 %0, {%1, %2};" : "=l"(r) : "f"(lo), "f"(hi)); return r;
}
__device__ __forceinline__ void unpack2(u64 v, float& lo, float& hi) {
    asm("mov.b64 {%0, %1}, %2;" : "=f"(lo), "=f"(hi) : "l"(v));
}
__device__ __forceinline__ u64 add2(u64 a, u64 b) {
    u64 d; asm("add.rn.f32x2 %0, %1, %2;" : "=l"(d) : "l"(a), "l"(b)); return d;
}
__device__ __forceinline__ u64 fma2(u64 a, u64 b, u64 c) {
    u64 d; asm("fma.rn.f32x2 %0, %1, %2, %3;" : "=l"(d) : "l"(a), "l"(b), "l"(c)); return d;
}
__device__ __forceinline__ unsigned smaddr(const void* p) {
    unsigned a;
    asm("{ .reg .u64 t; cvta.to.shared.u64 t, %1; cvt.u32.u64 %0, t; }" : "=r"(a) : "l"(p));
    return a;
}

#define MBAR_INIT(mb) \
    asm volatile("mbarrier.init.shared.b64 [%0], 1;" :: "r"(mb) : "memory")
#define MBAR_EXPECT(mb, bytes) \
    asm volatile("mbarrier.arrive.expect_tx.shared.b64 _, [%0], %1;" :: "r"(mb), "r"(bytes) : "memory")
#define BULK_1KB(dst, src, mb) \
    asm volatile("cp.async.bulk.shared::cluster.global.mbarrier::complete_tx::bytes [%0], [%1], %2, [%3];" \
                 :: "r"(dst), "l"(src), "r"(1024), "r"(mb) : "memory")
#define MBAR_WAITP(mb, ph) do {                                                   \
    unsigned _done;                                                               \
    asm volatile("{\n\t.reg .pred p;\n\t"                                         \
        "mbarrier.try_wait.parity.acquire.cta.shared::cta.b64 p, [%1], %2;\n\t"   \
        "selp.b32 %0, 1, 0, p;\n\t}"                                              \
        : "=r"(_done) : "r"(mb), "r"(ph) : "memory");                             \
    if (!_done) {                                                                 \
        asm volatile("{\n\t.reg .pred P1;\n\t"                                    \
            "WL_%=:\n\t"                                                          \
            "mbarrier.try_wait.parity.acquire.cta.shared::cta.b64 P1, [%0], %1;\n\t" \
            "@P1 bra.uni WD_%=;\n\t"                                              \
            "bra.uni WL_%=;\n\t"                                                  \
            "WD_%=:\n\t}"                                                         \
            :: "r"(mb), "r"(ph) : "memory");                                      \
    }                                                                             \
} while (0)

// Horizontal pass: forward masked DCT coefficients + inverse, in place.
// Lane holds columns {2q, 2q+1}; per kept coeff: local partial, 4-lane
// all-reduce (2x shfl_xor), back-substitute. Result is 4x true round trip
// (folded into stage-3 immediates).
template <int NR>
__device__ __forceinline__ void hpass(float (&A)[NR][2],
                                      const unsigned (&mask)[NR],
                                      const float (&Wl)[6][2])
{
#pragma unroll
    for (int k = 0; k < NR; ++k) {
        const unsigned m = mask[k];
        float Bv[6];
#pragma unroll
        for (int l = 0; l < 6; ++l) {
            if ((m >> l) & 1) {
                float p = (l == 0) ? (A[k][0] + A[k][1])
                                   : fmaf(A[k][1], Wl[l][1], A[k][0] * Wl[l][0]);
                p += __shfl_xor_sync(0xffffffffu, p, 1);
                p += __shfl_xor_sync(0xffffffffu, p, 2);
                Bv[l] = p;
            }
        }
#pragma unroll
        for (int jj = 0; jj < 2; ++jj) {
            float s = 0.f;
#pragma unroll
            for (int l = 0; l < 6; ++l)
                if ((m >> l) & 1)
                    s = fmaf(Bv[l], (l == 0) ? 0.5f : Wl[l][jj], s);
            A[k][jj] = s;
        }
    }
}

// Stage-1 accumulation for one row pair (rows P, 7-P) read from smem chunk CK,
// pair slot I. Rows stored per channel at slots ch*4 + 2I (row P) and
// ch*4 + 2I + 1 (row 7-P). P is a literal -> D[*][P] fold to immediates.
#define S1PAIR(CK, I, P)                                                        \
    {                                                                           \
        u64 ra = *(const u64*)&sm[CK][0 + 2*(I)    ][col];                      \
        u64 rb = *(const u64*)&sm[CK][0 + 2*(I) + 1][col];                      \
        u64 ga = *(const u64*)&sm[CK][4 + 2*(I)    ][col];                      \
        u64 gb = *(const u64*)&sm[CK][4 + 2*(I) + 1][col];                      \
        u64 ba = *(const u64*)&sm[CK][8 + 2*(I)    ][col];                      \
        u64 bb = *(const u64*)&sm[CK][8 + 2*(I) + 1][col];                      \
        u64 sr = add2(ra, rb), dr = fma2(rb, MIN1, ra);                         \
        u64 sg = add2(ga, gb), dg = fma2(gb, MIN1, ga);                         \
        u64 sb = add2(ba, bb), db = fma2(bb, MIN1, ba);                         \
        float srf[2], drf[2], sgf[2], dgf[2], sbf[2], dbf[2];                   \
        unpack2(sr, srf[0], srf[1]); unpack2(dr, drf[0], drf[1]);               \
        unpack2(sg, sgf[0], sgf[1]); unpack2(dg, dgf[0], dgf[1]);               \
        unpack2(sb, sbf[0], sbf[1]); unpack2(db, dbf[0], dbf[1]);               \
        _Pragma("unroll")                                                       \
        for (int jj = 0; jj < 2; ++jj) {                                        \
            float sy = fmaf(0.299f, srf[jj], fmaf(0.587f, sgf[jj], 0.114f * sbf[jj])); \
            float dy = fmaf(0.299f, drf[jj], fmaf(0.587f, dgf[jj], 0.114f * dbf[jj])); \
            AR[0][jj] += srf[jj];                                               \
            AR[2][jj] = fmaf(D[2][P], srf[jj], AR[2][jj]);                      \
            AR[1][jj] = fmaf(D[1][P], drf[jj], AR[1][jj]);                      \
            AG[0][jj] += sgf[jj];                                               \
            AG[2][jj] = fmaf(D[2][P], sgf[jj], AG[2][jj]);                      \
            AG[1][jj] = fmaf(D[1][P], dgf[jj], AG[1][jj]);                      \
            AB[0][jj] += sbf[jj];                                               \
            AB[2][jj] = fmaf(D[2][P], sbf[jj], AB[2][jj]);                      \
            AB[1][jj] = fmaf(D[1][P], dbf[jj], AB[1][jj]);                      \
            AY[0][jj] += sy;                                                    \
            AY[2][jj] = fmaf(D[2][P], sy, AY[2][jj]);                           \
            AY[4][jj] = fmaf(D[4][P], sy, AY[4][jj]);                           \
            AY[6][jj] = fmaf(D[6][P], sy, AY[6][jj]);                           \
            AY[1][jj] = fmaf(D[1][P], dy, AY[1][jj]);                           \
            AY[3][jj] = fmaf(D[3][P], dy, AY[3][jj]);                           \
            AY[5][jj] = fmaf(D[5][P], dy, AY[5][jj]);                           \
        }                                                                       \
    }

// CTA = 32 consecutive tiles (a contiguous 8x256 3-channel slab).
// Loads staged via cp.async.bulk -> smem (2 chunks of row pairs, pipelined),
// eliminating the per-thread 24-deep LDG front batch (L1tex queue contention).
// Compute: 4 threads/tile, luma split + even/odd symmetry (R6 structure).
__global__ void __launch_bounds__(128, 6)
jpeg_fused_kernel(const float* __restrict__ in, float* __restrict__ out)
{
    __shared__ __align__(16) float sm[2][12][256];
    __shared__ __align__(8) u64 mbar[2];

    const int tid = threadIdx.x;
    const int lt  = tid >> 2;      // local tile 0..31
    const int q   = tid & 3;       // column-pair lane within tile

    // D[k][n] = cos(pi/8 * (n+0.5) * k)
    const float D[8][8] = {
        { 1.f,  1.f,  1.f,  1.f,  1.f,  1.f,  1.f,  1.f},
        { CC1,  CC3,  CC5,  CC7, -CC7, -CC5, -CC3, -CC1},
        { CC2,  CC6, -CC6, -CC2, -CC2, -CC6,  CC6,  CC2},
        { CC3, -CC7, -CC1, -CC5,  CC5,  CC1,  CC7, -CC3},
        { CC4, -CC4, -CC4,  CC4,  CC4, -CC4, -CC4,  CC4},
        { CC5, -CC1,  CC7,  CC3, -CC3, -CC7,  CC1, -CC5},
        { CC6, -CC2,  CC2, -CC6, -CC6,  CC2, -CC2,  CC6},
        { CC7, -CC5,  CC3, -CC1,  CC1, -CC3,  CC5, -CC7}
    };
    const unsigned MRGB[3] = {0x0Fu, 0x07u, 0x03u};                              // 9
    const unsigned MY[7]   = {0x30u, 0x18u, 0x0Cu, 0x0Fu, 0x07u, 0x03u, 0x01u}; // 16

    float Wl[6][2];
#pragma unroll
    for (int l = 1; l < 6; ++l) {
        Wl[l][0] = (q & 2) ? ((q & 1) ? D[l][6] : D[l][4])
                           : ((q & 1) ? D[l][2] : D[l][0]);
        Wl[l][1] = (q & 2) ? ((q & 1) ? D[l][7] : D[l][5])
                           : ((q & 1) ? D[l][3] : D[l][1]);
    }

    const u64 MIN1 = pack2(-1.f, -1.f);

    const int S = 512 * 512;
    const int T0  = blockIdx.x * 32;        // first tile of this CTA
    const int b   = T0 >> 12;
    const int t0  = T0 & 4095;
    const int ty  = t0 >> 6;
    const int tx0 = t0 & 63;                // 0 or 32 (32 | 64)
    const size_t SB = (size_t)b * (3 * S) + (size_t)(ty * 8) * 512 + (size_t)tx0 * 8;

    const unsigned mb0 = smaddr(&mbar[0]);
    const unsigned mb1 = smaddr(&mbar[1]);

    if (tid == 0) {
        MBAR_INIT(mb0);
        MBAR_INIT(mb1);
    }
    __syncthreads();

    if (tid == 0) {
        // chunk0: row pairs (0,7),(1,6) -> slots [0,1,2,3] per channel
        // chunk1: row pairs (2,5),(3,4)
        const int rows0[4] = {0, 7, 1, 6};
        const int rows1[4] = {2, 5, 3, 4};
        MBAR_EXPECT(mb0, 12 * 1024);
#pragma unroll
        for (int ch = 0; ch < 3; ++ch)
#pragma unroll
            for (int i = 0; i < 4; ++i) {
                unsigned dst = smaddr(&sm[0][ch * 4 + i][0]);
                const float* src = in + SB + (size_t)ch * S + (size_t)rows0[i] * 512;
                BULK_1KB(dst, src, mb0);
            }
        MBAR_EXPECT(mb1, 12 * 1024);
#pragma unroll
        for (int ch = 0; ch < 3; ++ch)
#pragma unroll
            for (int i = 0; i < 4; ++i) {
                unsigned dst = smaddr(&sm[1][ch * 4 + i][0]);
                const float* src = in + SB + (size_t)ch * S + (size_t)rows1[i] * 512;
                BULK_1KB(dst, src, mb1);
            }
    }

    const int col = lt * 8 + q * 2;         // column within the 256-wide slab

    float AY[7][2];
    float AR[3][2], AG[3][2], AB[3][2];
#pragma unroll
    for (int k = 0; k < 7; ++k) { AY[k][0] = 0.f; AY[k][1] = 0.f; }
#pragma unroll
    for (int k = 0; k < 3; ++k) {
        AR[k][0] = 0.f; AR[k][1] = 0.f;
        AG[k][0] = 0.f; AG[k][1] = 0.f;
        AB[k][0] = 0.f; AB[k][1] = 0.f;
    }

    // ---- stage 1: two pipelined chunks ----
    MBAR_WAITP(mb0, 0);
    S1PAIR(0, 0, 0)     // rows (0,7), weights D[*][0]
    S1PAIR(0, 1, 1)     // rows (1,6), weights D[*][1]
    MBAR_WAITP(mb1, 0);
    S1PAIR(1, 0, 2)     // rows (2,5), weights D[*][2]
    S1PAIR(1, 1, 3)     // rows (3,4), weights D[*][3]

    // ---- stage 2: horizontal masked round trip per unit ----
    hpass<3>(AR, MRGB, Wl);
    hpass<3>(AG, MRGB, Wl);
    hpass<3>(AB, MRGB, Wl);
    hpass<7>(AY, MY,   Wl);

    // ---- stage 3: vertical inverse (k==0 -> 0.03125, else 0.0625*D[k][n]);
    //      out_c = idct(A_c) + idct(AY); coalesced stores ----
    float* o0 = out + (SB + (size_t)col);
#pragma unroll
    for (int p = 0; p < 4; ++p) {
        const int i0 = p * 512;
        const int i1 = (7 - p) * 512;
        float rA[2], rB[2], gA[2], gB[2], bA[2], bB[2];
#pragma unroll
        for (int jj = 0; jj < 2; ++jj) {
            float ey = 0.03125f * AY[0][jj];
            ey = fmaf(0.0625f * D[2][p], AY[2][jj], ey);
            ey = fmaf(0.0625f * D[4][p], AY[4][jj], ey);
            ey = fmaf(0.0625f * D[6][p], AY[6][jj], ey);
            float oy = 0.0625f * D[1][p] * AY[1][jj];
            oy = fmaf(0.0625f * D[3][p], AY[3][jj], oy);
            oy = fmaf(0.0625f * D[5][p], AY[5][jj], oy);
            const float yA = ey + oy, yB = ey - oy;

            float e = 0.03125f * AR[0][jj];
            e = fmaf(0.0625f * D[2][p], AR[2][jj], e);
            float o = 0.0625f * D[1][p] * AR[1][jj];
            rA[jj] = (e + o) + yA;  rB[jj] = (e - o) + yB;

            e = 0.03125f * AG[0][jj];
            e = fmaf(0.0625f * D[2][p], AG[2][jj], e);
            o = 0.0625f * D[1][p] * AG[1][jj];
            gA[jj] = (e + o) + yA;  gB[jj] = (e - o) + yB;

            e = 0.03125f * AB[0][jj];
            e = fmaf(0.0625f * D[2][p], AB[2][jj], e);
            o = 0.0625f * D[1][p] * AB[1][jj];
            bA[jj] = (e + o) + yA;  bB[jj] = (e - o) + yB;
        }
        *(float2*)(o0 + i0)         = make_float2(rA[0], rA[1]);
        *(float2*)(o0 + i0 + S)     = make_float2(gA[0], gA[1]);
        *(float2*)(o0 + i0 + 2 * S) = make_float2(bA[0], bA[1]);
        *(float2*)(o0 + i1)         = make_float2(rB[0], rB[1]);
        *(float2*)(o0 + i1 + S)     = make_float2(gB[0], gB[1]);
        *(float2*)(o0 + i1 + 2 * S) = make_float2(bB[0], bB[1]);
    }
}

extern "C" void kernel_launch(void* const* d_in, const int* in_sizes, int n_in,
                              void* d_out, int out_size)
{
    const float* in = (const float*)d_in[0];
    float* out = (float*)d_out;
    const int total = in_sizes[0];               // B*3*512*512
    const int B = total / (3 * 512 * 512);
    const int ctas = B * 128;                    // 32 tiles per CTA
    jpeg_fused_kernel<<<ctas, 128>>>(in, out);
}

// round 8
// speedup vs baseline: 1.1196x; 1.1196x over previous
#include <cuda_runtime.h>

// cos(pi*t/16) constants
#define CC1 0.98078528040323044913f
#define CC2 0.92387953251128675613f
#define CC3 0.83146961230254523708f
#define CC4 0.70710678118654752440f
#define CC5 0.55557023301960222474f
#define CC6 0.38268343236508977173f
#define CC7 0.19509032201612826785f

typedef unsigned long long u64;

__device__ __forceinline__ u64 pack2(float lo, float hi) {
    u64 r; asm("mov.b64 %0, {%1, %2};" : "=l"(r) : "f"(lo), "f"(hi)); return r;
}
__device__ __forceinline__ void unpack2(u64 v, float& lo, float& hi) {
    asm("mov.b64 {%0, %1}, %2;" : "=f"(lo), "=f"(hi) : "l"(v));
}
__device__ __forceinline__ u64 add2(u64 a, u64 b) {
    u64 d; asm("add.rn.f32x2 %0, %1, %2;" : "=l"(d) : "l"(a), "l"(b)); return d;
}
__device__ __forceinline__ u64 fma2(u64 a, u64 b, u64 c) {
    u64 d; asm("fma.rn.f32x2 %0, %1, %2, %3;" : "=l"(d) : "l"(a), "l"(b), "l"(c)); return d;
}

// Horizontal pass: forward masked DCT coefficients + inverse, in place.
// Lane holds columns {2q, 2q+1}; per kept coeff: local partial, 4-lane
// all-reduce (2x shfl_xor), back-substitute. Result is 4x true round trip
// (folded into stage-3 immediates). Wl[4][1] == -Wl[4][0] by construction;
// FFMA operand negation folds it to one register.
template <int NR>
__device__ __forceinline__ void hpass(float (&A)[NR][2],
                                      const unsigned (&mask)[NR],
                                      const float (&Wl)[6][2])
{
#pragma unroll
    for (int k = 0; k < NR; ++k) {
        const unsigned m = mask[k];
        float Bv[6];
#pragma unroll
        for (int l = 0; l < 6; ++l) {
            if ((m >> l) & 1) {
                float p = (l == 0) ? (A[k][0] + A[k][1])
                                   : fmaf(A[k][1], Wl[l][1], A[k][0] * Wl[l][0]);
                p += __shfl_xor_sync(0xffffffffu, p, 1);
                p += __shfl_xor_sync(0xffffffffu, p, 2);
                Bv[l] = p;
            }
        }
#pragma unroll
        for (int jj = 0; jj < 2; ++jj) {
            float s = 0.f;
#pragma unroll
            for (int l = 0; l < 6; ++l)
                if ((m >> l) & 1)
                    s = fmaf(Bv[l], (l == 0) ? 0.5f : Wl[l][jj], s);
            A[k][jj] = s;
        }
    }
}

// Four threads per 8x8 tile, lane q owns columns {2q, 2q+1}.
// Exact pipeline (no luma-split): RGB2YUV -> masked DCT round trip -> YUV2RGB,
// with even/odd row symmetry in both vertical stages.
// Register-capped to 64 -> 8 CTAs/SM.
__global__ void __launch_bounds__(128, 8)
jpeg_fused_kernel(const float* __restrict__ in, float* __restrict__ out, int nthr)
{
    const int g = blockIdx.x * blockDim.x + threadIdx.x;
    if (g >= nthr) return;
    const int tile = g >> 2;
    const int q = g & 3;

    // D[k][n] = cos(pi/8 * (n+0.5) * k)
    const float D[8][8] = {
        { 1.f,  1.f,  1.f,  1.f,  1.f,  1.f,  1.f,  1.f},
        { CC1,  CC3,  CC5,  CC7, -CC7, -CC5, -CC3, -CC1},
        { CC2,  CC6, -CC6, -CC2, -CC2, -CC6,  CC6,  CC2},
        { CC3, -CC7, -CC1, -CC5,  CC5,  CC1,  CC7, -CC3},
        { CC4, -CC4, -CC4,  CC4,  CC4, -CC4, -CC4,  CC4},
        { CC5, -CC1,  CC7,  CC3, -CC3, -CC7,  CC1, -CC5},
        { CC6, -CC2,  CC2, -CC6, -CC6,  CC2, -CC2,  CC6},
        { CC7, -CC5,  CC3, -CC1,  CC1, -CC3,  CC5, -CC7}
    };

    // kept-coefficient prefix bitmasks per row
    const unsigned MYF[7] = {0x3Fu, 0x1Fu, 0x0Fu, 0x0Fu, 0x07u, 0x03u, 0x01u}; // Y: 25
    const unsigned MUV[3] = {0x0Fu, 0x07u, 0x03u};                              // U/V: 9

    // Lane-dependent horizontal constants Wl[l][jj] = D[l][2q+jj], l=1..5.
    // Row 4: D[4] = {C4,-C4,-C4,C4,...} -> Wl[4][1] = -Wl[4][0] (1 live reg).
    float Wl[6][2];
#pragma unroll
    for (int l = 1; l < 6; ++l) {
        if (l == 4) continue;
        Wl[l][0] = (q & 2) ? ((q & 1) ? D[l][6] : D[l][4])
                           : ((q & 1) ? D[l][2] : D[l][0]);
        Wl[l][1] = (q & 2) ? ((q & 1) ? D[l][7] : D[l][5])
                           : ((q & 1) ? D[l][3] : D[l][1]);
    }
    {
        float w4 = (q & 1) ? -CC4 : CC4;
        Wl[4][0] = w4;
        Wl[4][1] = -w4;
    }

    const u64 MIN1 = pack2(-1.f, -1.f);

    const int W = 512;
    const int S = 512 * 512;

    const int b  = tile >> 12;
    const int t  = tile & 4095;
    const int ty = t >> 6;
    const int tx = t & 63;

    const size_t off = (size_t)b * (3 * S) + (size_t)(ty * 8) * W
                     + (size_t)(tx * 8) + (size_t)(q * 2);
    const float* p0 = in + off;
    float* o0 = out + off;

    float Ay[7][2];
    float Au[3][2];
    float Av[3][2];
#pragma unroll
    for (int k = 0; k < 7; ++k) { Ay[k][0] = 0.f; Ay[k][1] = 0.f; }
#pragma unroll
    for (int k = 0; k < 3; ++k) { Au[k][0] = 0.f; Au[k][1] = 0.f;
                                  Av[k][0] = 0.f; Av[k][1] = 0.f; }

    // ---- stage 1: row pairs (p, 7-p): packed s/d on RGB, scalar YUV of s/d,
    //      even/odd vertical DCT accumulate ----
#pragma unroll
    for (int p = 0; p < 4; ++p) {
        const int i0 = p * W;
        const int i1 = (7 - p) * W;
        u64 sr, dr, sg, dg, sb, db;
        {
            u64 a = *(const u64*)(p0 + i0);
            u64 c = *(const u64*)(p0 + i1);
            sr = add2(a, c); dr = fma2(c, MIN1, a);
        }
        {
            u64 a = *(const u64*)(p0 + i0 + S);
            u64 c = *(const u64*)(p0 + i1 + S);
            sg = add2(a, c); dg = fma2(c, MIN1, a);
        }
        {
            u64 a = *(const u64*)(p0 + i0 + 2 * S);
            u64 c = *(const u64*)(p0 + i1 + 2 * S);
            sb = add2(a, c); db = fma2(c, MIN1, a);
        }
        float srf[2], drf[2], sgf[2], dgf[2], sbf[2], dbf[2];
        unpack2(sr, srf[0], srf[1]); unpack2(dr, drf[0], drf[1]);
        unpack2(sg, sgf[0], sgf[1]); unpack2(dg, dgf[0], dgf[1]);
        unpack2(sb, sbf[0], sbf[1]); unpack2(db, dbf[0], dbf[1]);

#pragma unroll
        for (int jj = 0; jj < 2; ++jj) {
            // YUV of s and d (linearity; all FFMA-imm forms)
            float sy = fmaf(0.299f,    srf[jj], fmaf(0.587f,    sgf[jj],  0.114f   * sbf[jj]));
            float su = fmaf(-0.14713f, srf[jj], fmaf(-0.28886f, sgf[jj],  0.436f   * sbf[jj]));
            float sv = fmaf(0.615f,    srf[jj], fmaf(-0.51499f, sgf[jj], -0.10001f * sbf[jj]));
            float dy = fmaf(0.299f,    drf[jj], fmaf(0.587f,    dgf[jj],  0.114f   * dbf[jj]));
            float du = fmaf(-0.14713f, drf[jj], fmaf(-0.28886f, dgf[jj],  0.436f   * dbf[jj]));
            float dv = fmaf(0.615f,    drf[jj], fmaf(-0.51499f, dgf[jj], -0.10001f * dbf[jj]));
            // even k consume s, odd k consume d
            Ay[0][jj] += sy;
            Ay[2][jj] = fmaf(D[2][p], sy, Ay[2][jj]);
            Ay[4][jj] = fmaf(D[4][p], sy, Ay[4][jj]);
            Ay[6][jj] = fmaf(D[6][p], sy, Ay[6][jj]);
            Ay[1][jj] = fmaf(D[1][p], dy, Ay[1][jj]);
            Ay[3][jj] = fmaf(D[3][p], dy, Ay[3][jj]);
            Ay[5][jj] = fmaf(D[5][p], dy, Ay[5][jj]);
            Au[0][jj] += su;
            Au[2][jj] = fmaf(D[2][p], su, Au[2][jj]);
            Au[1][jj] = fmaf(D[1][p], du, Au[1][jj]);
            Av[0][jj] += sv;
            Av[2][jj] = fmaf(D[2][p], sv, Av[2][jj]);
            Av[1][jj] = fmaf(D[1][p], dv, Av[1][jj]);
        }
    }

    // ---- stage 2: horizontal masked round trip per channel ----
    hpass<7>(Ay, MYF, Wl);
    hpass<3>(Au, MUV, Wl);
    hpass<3>(Av, MUV, Wl);

    // ---- stage 3: even/odd vertical inverse (k==0 -> 0.03125, else 0.0625*D[k][n])
    //      + YUV2RGB + coalesced stores ----
#pragma unroll
    for (int p = 0; p < 4; ++p) {
        const int i0 = p * W;
        const int i1 = (7 - p) * W;
        float rA[2], rB[2], gA[2], gB[2], bA[2], bB[2];
#pragma unroll
        for (int jj = 0; jj < 2; ++jj) {
            float ey = 0.03125f * Ay[0][jj];
            ey = fmaf(0.0625f * D[2][p], Ay[2][jj], ey);
            ey = fmaf(0.0625f * D[4][p], Ay[4][jj], ey);
            ey = fmaf(0.0625f * D[6][p], Ay[6][jj], ey);
            float oy = 0.0625f * D[1][p] * Ay[1][jj];
            oy = fmaf(0.0625f * D[3][p], Ay[3][jj], oy);
            oy = fmaf(0.0625f * D[5][p], Ay[5][jj], oy);
            float eu = 0.03125f * Au[0][jj];
            eu = fmaf(0.0625f * D[2][p], Au[2][jj], eu);
            float ou = 0.0625f * D[1][p] * Au[1][jj];
            float ev = 0.03125f * Av[0][jj];
            ev = fmaf(0.0625f * D[2][p], Av[2][jj], ev);
            float ov = 0.0625f * D[1][p] * Av[1][jj];

            float yA = ey + oy, yB = ey - oy;
            float uA = eu + ou, uB = eu - ou;
            float vA = ev + ov, vB = ev - ov;

            rA[jj] = fmaf(1.13983f, vA, yA);
            gA[jj] = fmaf(-0.5806f, vA, fmaf(-0.39465f, uA, yA));
            bA[jj] = fmaf(2.03211f, uA, yA);
            rB[jj] = fmaf(1.13983f, vB, yB);
            gB[jj] = fmaf(-0.5806f, vB, fmaf(-0.39465f, uB, yB));
            bB[jj] = fmaf(2.03211f, uB, yB);
        }
        *(float2*)(o0 + i0)         = make_float2(rA[0], rA[1]);
        *(float2*)(o0 + i0 + S)     = make_float2(gA[0], gA[1]);
        *(float2*)(o0 + i0 + 2 * S) = make_float2(bA[0], bA[1]);
        *(float2*)(o0 + i1)         = make_float2(rB[0], rB[1]);
        *(float2*)(o0 + i1 + S)     = make_float2(gB[0], gB[1]);
        *(float2*)(o0 + i1 + 2 * S) = make_float2(bB[0], bB[1]);
    }
}

extern "C" void kernel_launch(void* const* d_in, const int* in_sizes, int n_in,
                              void* d_out, int out_size)
{
    const float* in = (const float*)d_in[0];
    float* out = (float*)d_out;
    const int total = in_sizes[0];               // B*3*512*512
    const int B = total / (3 * 512 * 512);
    const int nthr = B * 64 * 64 * 4;            // 4 threads per tile
    const int threads = 128;
    const int blocks = (nthr + threads - 1) / threads;
    jpeg_fused_kernel<<<blocks, threads>>>(in, out, nthr);
}

// round 9
// speedup vs baseline: 1.1366x; 1.0152x over previous
#include <cuda_runtime.h>

// cos(pi*t/16) constants
#define CC1 0.98078528040323044913f
#define CC2 0.92387953251128675613f
#define CC3 0.83146961230254523708f
#define CC4 0.70710678118654752440f
#define CC5 0.55557023301960222474f
#define CC6 0.38268343236508977173f
#define CC7 0.19509032201612826785f

typedef unsigned long long u64;

__device__ __forceinline__ u64 pack2(float lo, float hi) {
    u64 r; asm("mov.b64 %0, {%1, %2};" : "=l"(r) : "f"(lo), "f"(hi)); return r;
}
__device__ __forceinline__ void unpack2(u64 v, float& lo, float& hi) {
    asm("mov.b64 {%0, %1}, %2;" : "=f"(lo), "=f"(hi) : "l"(v));
}
__device__ __forceinline__ u64 add2(u64 a, u64 b) {
    u64 d; asm("add.rn.f32x2 %0, %1, %2;" : "=l"(d) : "l"(a), "l"(b)); return d;
}
__device__ __forceinline__ u64 mul2(u64 a, u64 b) {
    u64 d; asm("mul.rn.f32x2 %0, %1, %2;" : "=l"(d) : "l"(a), "l"(b)); return d;
}
__device__ __forceinline__ u64 fma2(u64 a, u64 b, u64 c) {
    u64 d; asm("fma.rn.f32x2 %0, %1, %2, %3;" : "=l"(d) : "l"(a), "l"(b), "l"(c)); return d;
}

// Packed accumulate with compile-time sign: A += sgn * X * C  (C = packed magnitude)
#define ACC(A, X, K, P)                                                \
    do {                                                               \
        if (SGN[K][P] > 0) (A) = fma2((X), PCC[IDX[K][P]], (A));       \
        else (A) = fma2(mul2((X), PCC[IDX[K][P]]), MIN1, (A));         \
    } while (0)

// Horizontal pass on packed rows: forward masked DCT + inverse, in place.
// Wl is PRE-SCALED by 0.25, so the round trip carries the 1/16 IDCT factor
// for l>=1 paths; the l==0 path uses the 0.03125 immediate (=0.125/4).
template <int NR>
__device__ __forceinline__ void hpassP(u64 (&A)[NR],
                                       const unsigned (&mask)[NR],
                                       const float (&Wl)[6][2])
{
#pragma unroll
    for (int k = 0; k < NR; ++k) {
        const unsigned m = mask[k];
        float a0, a1;
        unpack2(A[k], a0, a1);
        float Bv[6];
#pragma unroll
        for (int l = 0; l < 6; ++l) {
            if ((m >> l) & 1) {
                float p = (l == 0) ? (a0 + a1)
                                   : fmaf(a1, Wl[l][1], a0 * Wl[l][0]);
                p += __shfl_xor_sync(0xffffffffu, p, 1);
                p += __shfl_xor_sync(0xffffffffu, p, 2);
                Bv[l] = p;
            }
        }
        float s0 = 0.f, s1 = 0.f;
#pragma unroll
        for (int l = 0; l < 6; ++l) {
            if ((m >> l) & 1) {
                if (l == 0) { s0 = fmaf(Bv[0], 0.03125f, s0); s1 = fmaf(Bv[0], 0.03125f, s1); }
                else        { s0 = fmaf(Bv[l], Wl[l][0], s0); s1 = fmaf(Bv[l], Wl[l][1], s1); }
            }
        }
        A[k] = pack2(s0, s1);
    }
}

// Four threads per 8x8 tile, lane q owns columns {2q, 2q+1} as ONE f32x2.
// Luma split: out_c = T9(x_c) + DeltaT16(y); no output color conversion.
// Stages 1 & 3 fully packed (FFMA2: 1 issue slot per 2 math); stage 2 scalar.
__global__ void __launch_bounds__(128, 6)
jpeg_fused_kernel(const float* __restrict__ in, float* __restrict__ out, int nthr)
{
    const int g = blockIdx.x * blockDim.x + threadIdx.x;
    if (g >= nthr) return;
    const int tile = g >> 2;
    const int q = g & 3;

    // D[k][n] = cos(pi/8 * (n+0.5) * k)
    const float D[8][8] = {
        { 1.f,  1.f,  1.f,  1.f,  1.f,  1.f,  1.f,  1.f},
        { CC1,  CC3,  CC5,  CC7, -CC7, -CC5, -CC3, -CC1},
        { CC2,  CC6, -CC6, -CC2, -CC2, -CC6,  CC6,  CC2},
        { CC3, -CC7, -CC1, -CC5,  CC5,  CC1,  CC7, -CC3},
        { CC4, -CC4, -CC4,  CC4,  CC4, -CC4, -CC4,  CC4},
        { CC5, -CC1,  CC7,  CC3, -CC3, -CC7,  CC1, -CC5},
        { CC6, -CC2,  CC2, -CC6, -CC6,  CC2, -CC2,  CC6},
        { CC7, -CC5,  CC3, -CC1,  CC1, -CC3,  CC5, -CC7}
    };
    // |D[k][p]| = CC_{IDX[k][p]}, sign = SGN[k][p], for p = 0..3 (k = 0 unused)
    const int IDX[7][4] = {
        {0,0,0,0}, {1,3,5,7}, {2,6,6,2}, {3,7,1,5}, {4,4,4,4}, {5,1,7,3}, {6,2,2,6}
    };
    const int SGN[7][4] = {
        {1,1,1,1}, {1,1,1,1}, {1,1,-1,-1}, {1,-1,-1,-1}, {1,-1,-1,1}, {1,-1,1,1}, {1,-1,1,-1}
    };
    const float CCv[8] = {1.f, CC1, CC2, CC3, CC4, CC5, CC6, CC7};

    // Packed broadcast magnitudes (serve stage 1 AND stage 3 — raw scale)
    u64 PCC[8];
#pragma unroll
    for (int i = 1; i < 8; ++i) PCC[i] = pack2(CCv[i], CCv[i]);
    const u64 MIN1 = pack2(-1.f, -1.f);

    // kept-coefficient bitmasks per row (luma-split)
    const unsigned MUV[3] = {0x0Fu, 0x07u, 0x03u};                               // 9
    const unsigned MYD[7] = {0x30u, 0x18u, 0x0Cu, 0x0Fu, 0x07u, 0x03u, 0x01u};  // 16

    // Lane-dependent horizontal constants, PRE-SCALED by 0.25:
    // Wl[l][jj] = 0.25 * D[l][2q+jj], l = 1..5.  Row 4: Wl[4][1] = -Wl[4][0].
    float Wl[6][2];
#pragma unroll
    for (int l = 1; l < 6; ++l) {
        if (l == 4) continue;
        Wl[l][0] = 0.25f * ((q & 2) ? ((q & 1) ? D[l][6] : D[l][4])
                                    : ((q & 1) ? D[l][2] : D[l][0]));
        Wl[l][1] = 0.25f * ((q & 2) ? ((q & 1) ? D[l][7] : D[l][5])
                                    : ((q & 1) ? D[l][3] : D[l][1]));
    }
    {
        float w4 = (q & 1) ? -0.25f * CC4 : 0.25f * CC4;
        Wl[4][0] = w4;
        Wl[4][1] = -w4;
    }

    const int W = 512;
    const int S = 512 * 512;

    const int b  = tile >> 12;
    const int t  = tile & 4095;
    const int ty = t >> 6;
    const int tx = t & 63;

    const size_t off = (size_t)b * (3 * S) + (size_t)(ty * 8) * W
                     + (size_t)(tx * 8) + (size_t)(q * 2);
    const float* p0 = in + off;
    float* o0 = out + off;

    // Packed accumulators: luma rows 0-6, R/G/B rows 0-2
    u64 AY[7], AR[3], AG[3], AB[3];
#pragma unroll
    for (int k = 0; k < 7; ++k) AY[k] = 0ull;
#pragma unroll
    for (int k = 0; k < 3; ++k) { AR[k] = 0ull; AG[k] = 0ull; AB[k] = 0ull; }

    // ---- stage 1: row pairs (p, 7-p): packed s/d, scalar luma, packed accumulate ----
#pragma unroll
    for (int p = 0; p < 4; ++p) {
        const int i0 = p * W;
        const int i1 = (7 - p) * W;
        u64 sr, dr, sg, dg, sb, db;
        {
            u64 a = *(const u64*)(p0 + i0);
            u64 c = *(const u64*)(p0 + i1);
            sr = add2(a, c); dr = fma2(c, MIN1, a);
        }
        {
            u64 a = *(const u64*)(p0 + i0 + S);
            u64 c = *(const u64*)(p0 + i1 + S);
            sg = add2(a, c); dg = fma2(c, MIN1, a);
        }
        {
            u64 a = *(const u64*)(p0 + i0 + 2 * S);
            u64 c = *(const u64*)(p0 + i1 + 2 * S);
            sb = add2(a, c); db = fma2(c, MIN1, a);
        }
        // scalar luma of s and d (FFMA-imm), then repack
        float x0, x1, y0, y1, z0, z1, w0, w1, v0, v1, u0, u1;
        unpack2(sr, x0, x1); unpack2(sg, y0, y1); unpack2(sb, z0, z1);
        unpack2(dr, w0, w1); unpack2(dg, v0, v1); unpack2(db, u0, u1);
        u64 sy = pack2(fmaf(0.299f, x0, fmaf(0.587f, y0, 0.114f * z0)),
                       fmaf(0.299f, x1, fmaf(0.587f, y1, 0.114f * z1)));
        u64 dy = pack2(fmaf(0.299f, w0, fmaf(0.587f, v0, 0.114f * u0)),
                       fmaf(0.299f, w1, fmaf(0.587f, v1, 0.114f * u1)));

        // packed accumulation (even rows <- s, odd rows <- d)
        AY[0] = add2(AY[0], sy);
        ACC(AY[2], sy, 2, p); ACC(AY[4], sy, 4, p); ACC(AY[6], sy, 6, p);
        ACC(AY[1], dy, 1, p); ACC(AY[3], dy, 3, p); ACC(AY[5], dy, 5, p);
        AR[0] = add2(AR[0], sr); ACC(AR[2], sr, 2, p); ACC(AR[1], dr, 1, p);
        AG[0] = add2(AG[0], sg); ACC(AG[2], sg, 2, p); ACC(AG[1], dg, 1, p);
        AB[0] = add2(AB[0], sb); ACC(AB[2], sb, 2, p); ACC(AB[1], db, 1, p);
    }

    // ---- stage 2: horizontal masked round trip (scalar, 0.25-scaled Wl) ----
    hpassP<3>(AR, MUV, Wl);
    hpassP<3>(AG, MUV, Wl);
    hpassP<3>(AB, MUV, Wl);
    hpassP<7>(AY, MYD, Wl);

    // Row-0 vertical-inverse weight is 0.5 (vs 1.0 for D-rows): halve once.
    {
        float a, c;
        unpack2(AY[0], a, c); AY[0] = pack2(0.5f * a, 0.5f * c);
        unpack2(AR[0], a, c); AR[0] = pack2(0.5f * a, 0.5f * c);
        unpack2(AG[0], a, c); AG[0] = pack2(0.5f * a, 0.5f * c);
        unpack2(AB[0], a, c); AB[0] = pack2(0.5f * a, 0.5f * c);
    }

    // ---- stage 3: packed even/odd vertical inverse; out_c = idct(A_c) + idct(AY) ----
#pragma unroll
    for (int p = 0; p < 4; ++p) {
        const int i0 = p * W;
        const int i1 = (7 - p) * W;

        u64 e = AY[0];
        ACC(e, AY[2], 2, p); ACC(e, AY[4], 4, p); ACC(e, AY[6], 6, p);
        u64 o = mul2(AY[1], PCC[IDX[1][p]]);          // SGN[1][p] always +
        ACC(o, AY[3], 3, p); ACC(o, AY[5], 5, p);
        const u64 yA = add2(e, o);
        const u64 yB = fma2(o, MIN1, e);

        u64 ec, oc;
        ec = AR[0]; ACC(ec, AR[2], 2, p);
        oc = mul2(AR[1], PCC[IDX[1][p]]);
        *(u64*)(o0 + i0)         = add2(add2(ec, oc), yA);
        *(u64*)(o0 + i1)         = add2(fma2(oc, MIN1, ec), yB);

        ec = AG[0]; ACC(ec, AG[2], 2, p);
        oc = mul2(AG[1], PCC[IDX[1][p]]);
        *(u64*)(o0 + i0 + S)     = add2(add2(ec, oc), yA);
        *(u64*)(o0 + i1 + S)     = add2(fma2(oc, MIN1, ec), yB);

        ec = AB[0]; ACC(ec, AB[2], 2, p);
        oc = mul2(AB[1], PCC[IDX[1][p]]);
        *(u64*)(o0 + i0 + 2 * S) = add2(add2(ec, oc), yA);
        *(u64*)(o0 + i1 + 2 * S) = add2(fma2(oc, MIN1, ec), yB);
    }
}

extern "C" void kernel_launch(void* const* d_in, const int* in_sizes, int n_in,
                              void* d_out, int out_size)
{
    const float* in = (const float*)d_in[0];
    float* out = (float*)d_out;
    const int total = in_sizes[0];               // B*3*512*512
    const int B = total / (3 * 512 * 512);
    const int nthr = B * 64 * 64 * 4;            // 4 threads per tile
    const int threads = 128;
    const int blocks = (nthr + threads - 1) / threads;
    jpeg_fused_kernel<<<blocks, threads>>>(in, out, nthr);
}